// round 14
// baseline (speedup 1.0000x reference)
#include <cuda_runtime.h>
#include <cfloat>

// Problem dims (fixed): N=4, T=24, C=4, H=W=256
#define N_ 4
#define T_ 24
#define C_ 4
#define HW 65536
#define NPLANES (N_*T_*C_)   // 384
#define NIMG (N_*T_)         // 96
#define OUT_ELEMS (NPLANES*HW)
#define PAIR_STRIDE (2*HW)

#define ROWS 32              // K1 source rows per slab
#define SLABS (256/ROWS)     // 8
#define K1GRID (NPLANES*SLABS)       // 3072
#define SROWS2 32            // K2 rows per slab
#define SSLABS2 (256/SROWS2) // 8
#define K2GRID (NIMG*SSLABS2)        // 768
#define K2_PER_IMG SSLABS2           // 8
#define CNT_TARGET (3*SLABS)         // 24 (c<3 planes only)

__device__ float g_smin[NPLANES * SLABS];
__device__ float g_smax[NPLANES * SLABS];
__device__ int   g_tidx[N_];
// Flow-control state (zero-init at load; protocol restores zeros each launch)
__device__ int   g_cnt[NIMG];
__device__ int   g_done[NIMG];
__device__ int   g_tcnt;
__device__ int   g_tdone;

__device__ __forceinline__ void poll_geq(const int* p, int target) {
    while (true) {
        int v;
        asm volatile("ld.global.acquire.gpu.b32 %0, [%1];" : "=r"(v) : "l"(p));
        if (v >= target) break;
        __nanosleep(200);
    }
}

__device__ __forceinline__ float4 ld_guard(const float4* __restrict__ row, int A) {
    return ((unsigned)A < 64u) ? row[A] : make_float4(0.f, 0.f, 0.f, 0.f);
}

template<int OFF>
__device__ __forceinline__ float4 hblend(const float4* __restrict__ row, int A,
                                         float wxc, float wx) {
    const float4 v = ld_guard(row, A);
    const float4 w = ld_guard(row, A + 1);
    const float e0 = (OFF == 0) ? v.x : (OFF == 1) ? v.y : (OFF == 2) ? v.z : v.w;
    const float e1 = (OFF == 0) ? v.y : (OFF == 1) ? v.z : (OFF == 2) ? v.w : w.x;
    const float e2 = (OFF == 0) ? v.z : (OFF == 1) ? v.w : (OFF == 2) ? w.x : w.y;
    const float e3 = (OFF == 0) ? v.w : (OFF == 1) ? w.x : (OFF == 2) ? w.y : w.z;
    const float e4 = (OFF == 0) ? w.x : (OFF == 1) ? w.y : (OFF == 2) ? w.z : w.w;
    float4 h;
    h.x = wxc * e0 + wx * e1;
    h.y = wxc * e1 + wx * e2;
    h.z = wxc * e2 + wx * e3;
    h.w = wxc * e3 + wx * e4;
    return h;
}

__device__ __forceinline__ float4 vblend(float4 h0, float4 h1, float wyc, float wy) {
    float4 o;
    o.x = wyc * h0.x + wy * h1.x;
    o.y = wyc * h0.y + wy * h1.y;
    o.z = wyc * h0.z + wy * h1.z;
    o.w = wyc * h0.w + wy * h1.w;
    return o;
}

template<int OFF>
__device__ __forceinline__ void translate_body(
    const float4* __restrict__ sraw,    // [33][64]
    float4* __restrict__ dst4,
    int r0, int DXd, int DY,
    float wx, float wxc, float wy, float wyc, int tid)
{
    const int istart = max(0, r0 - DY);
    const int iend   = min(256, r0 + ROWS - DY);
    const int nrows  = iend - istart;

    if (nrows == ROWS) {
        // Two independent quad-row chains: rows 4g..4g+3 and 4g+16..4g+19.
        // 5 hblends (10 LDS) per 4 outputs.
        const int c4 = tid & 63;
        const int g  = tid >> 6;          // 0..3
        const int A  = c4 + DXd;
        #pragma unroll
        for (int half = 0; half < 2; half++) {
            const int rA = 4 * g + half * 16;   // source rows rA..rA+4 (<=32)
            float4 h[5];
            #pragma unroll
            for (int k = 0; k < 5; k++)
                h[k] = hblend<OFF>(sraw + (rA + k) * 64, A, wxc, wx);
            #pragma unroll
            for (int k = 0; k < 4; k++)
                __stcs(dst4 + (istart + rA + k) * 64 + c4,
                       vblend(h[k], h[k + 1], wyc, wy));
        }
    } else {
        for (int q = tid; q < nrows * 64; q += 256) {
            const int rr = q >> 6;
            const int c4 = q & 63;
            const int i = istart + rr;
            const int l0 = i + DY - r0;
            const int A = c4 + DXd;
            const float4 h0 = hblend<OFF>(sraw + l0 * 64, A, wxc, wx);
            const float4 h1 = hblend<OFF>(sraw + (l0 + 1) * 64, A, wxc, wx);
            __stcs(dst4 + i * 64 + c4, vblend(h0, h1, wyc, wy));
        }
    }

    // Boundary row i = -DY-1 (only valid tap is source row 0, weight wy)
    if (r0 == 0 && DY <= -1) {
        const int i = -DY - 1;
        if (i < 256 && tid < 64) {
            const float4 h0 = hblend<OFF>(sraw, tid + DXd, wxc, wx);
            float4 o;
            o.x = wy * h0.x; o.y = wy * h0.y; o.z = wy * h0.z; o.w = wy * h0.w;
            __stcs(dst4 + i * 64 + tid, o);
        }
    }
}

// ---------------------------------------------------------------------------
// Fused kernel: blocks [0, 3072) = translate (+min/max for c<3), publishing
// per-image counters; blocks [3072, 3840) = slice, acquire-polling counters.
// ---------------------------------------------------------------------------
__global__ __launch_bounds__(256) void k_fused(
    const float* __restrict__ x,
    const int* __restrict__ dates,
    const float* __restrict__ thetas,
    float* __restrict__ out,
    float* __restrict__ xp)
{
    const int tid = threadIdx.x;

    if (blockIdx.x < K1GRID) {
        // ================= K1 path =================
        __shared__ float4 sraw[(ROWS + 1) * 64];
        __shared__ float smin[8], smax[8];

        const int plane = blockIdx.x >> 3;        // / SLABS
        const int slab  = blockIdx.x & (SLABS - 1);
        const int r0 = slab * ROWS;
        const int b = plane >> 2;
        const bool do_mm = ((plane & 3) != 3);    // channel 3 min/max unused
        const float* __restrict__ src = x + (size_t)plane * HW;
        float4* __restrict__ dst4 = reinterpret_cast<float4*>(out + (size_t)plane * HW);

        if (blockIdx.x < N_ && tid == 0) {
            const int n = blockIdx.x;
            int best = 0;
            int bd = abs(182 - dates[n * T_]);
            #pragma unroll
            for (int t = 1; t < T_; t++) {
                int d = abs(182 - dates[n * T_ + t]);
                if (d < bd) { bd = d; best = t; }
            }
            g_tidx[n] = best;
            __threadfence();
            atomicAdd(&g_tcnt, 1);
        }

        const float tx = thetas[2 * b + 0];
        const float ty = thetas[2 * b + 1];
        const float fDX = floorf(-tx);
        const float fDY = floorf(-ty);
        const int DX = (int)fDX;
        const int DY = (int)fDY;
        const float wx = -tx - fDX;
        const float wy = -ty - fDY;
        const float wxc = 1.f - wx;
        const float wyc = 1.f - wy;
        const int DXd = DX >> 2;
        const int off = DX & 3;

        // ---- Stage rows r0..r0+31 (unguarded, 2 batches of 4 front-batched
        //      LDG.128) + guarded tail row r0+32. Fused min/max for c<3.
        float vmin = FLT_MAX, vmax = -FLT_MAX;
        const float4* __restrict__ src4 = reinterpret_cast<const float4*>(src);
        #pragma unroll
        for (int batch = 0; batch < 2; batch++) {
            float4 vv[4];
            #pragma unroll
            for (int k = 0; k < 4; k++)
                vv[k] = __ldg(src4 + r0 * 64 + tid + (batch * 4 + k) * 256);
            #pragma unroll
            for (int k = 0; k < 4; k++) {
                sraw[tid + (batch * 4 + k) * 256] = vv[k];
                if (do_mm) {
                    vmin = fminf(vmin, fminf(fminf(vv[k].x, vv[k].y), fminf(vv[k].z, vv[k].w)));
                    vmax = fmaxf(vmax, fmaxf(fmaxf(vv[k].x, vv[k].y), fmaxf(vv[k].z, vv[k].w)));
                }
            }
        }
        if (tid < 64) {
            const int gr = r0 + ROWS;
            float4 v = make_float4(0.f, 0.f, 0.f, 0.f);
            if (gr < 256) v = __ldg(src4 + gr * 64 + tid);
            sraw[ROWS * 64 + tid] = v;
        }
        __syncthreads();

        switch (off) {
            case 0: translate_body<0>(sraw, dst4, r0, DXd, DY, wx, wxc, wy, wyc, tid); break;
            case 1: translate_body<1>(sraw, dst4, r0, DXd, DY, wx, wxc, wy, wyc, tid); break;
            case 2: translate_body<2>(sraw, dst4, r0, DXd, DY, wx, wxc, wy, wyc, tid); break;
            default: translate_body<3>(sraw, dst4, r0, DXd, DY, wx, wxc, wy, wyc, tid); break;
        }

        // ---- Zero-fill rows no block computes ----
        {
            const int lo = max(0, -DY - 1);
            const int hi = min(256, 256 - DY);
            const float4 z = make_float4(0.f, 0.f, 0.f, 0.f);
            #pragma unroll
            for (int k = 0; k < 8; k++) {
                const int q = tid + k * 256;
                const int r = r0 + (q >> 6);
                if (r < lo || r >= hi)
                    __stcs(dst4 + r * 64 + (q & 63), z);
            }
        }

        // ---- Block min/max -> per-slab partial + publish (c<3 only) ----
        if (do_mm) {
            #pragma unroll
            for (int o = 16; o; o >>= 1) {
                vmin = fminf(vmin, __shfl_xor_sync(0xffffffffu, vmin, o));
                vmax = fmaxf(vmax, __shfl_xor_sync(0xffffffffu, vmax, o));
            }
            const int w = tid >> 5, l = tid & 31;
            if (l == 0) { smin[w] = vmin; smax[w] = vmax; }
            __syncthreads();
            if (tid == 0) {
                float m = smin[0], M = smax[0];
                #pragma unroll
                for (int k = 1; k < 8; k++) {
                    m = fminf(m, smin[k]);
                    M = fmaxf(M, smax[k]);
                }
                g_smin[plane * SLABS + slab] = m;
                g_smax[plane * SLABS + slab] = M;
                __threadfence();
                atomicAdd(&g_cnt[plane >> 2], 1);
            }
        }
    } else {
        // ================= K2 path =================
        __shared__ float s_m[6], s_M[6];
        __shared__ int s_pref;

        const int k2   = blockIdx.x - K1GRID;
        const int p    = k2 >> 3;                // / SSLABS2
        const int slab = k2 & (SSLABS2 - 1);
        const int n = p / T_;
        const int r0 = slab * SROWS2;

        if (tid == 0) {
            poll_geq(&g_tcnt, N_);
            const int pref = n * T_ + g_tidx[n];
            s_pref = pref;
            poll_geq(&g_cnt[p], CNT_TARGET);
            if (pref != p) poll_geq(&g_cnt[pref], CNT_TARGET);
            // Done tokens: last poller of a counter resets it for next launch.
            {
                const int tgt_p = (p == pref) ? (T_ * K2_PER_IMG) : K2_PER_IMG;
                int old = atomicAdd(&g_done[p], 1);
                if (old == tgt_p - 1) { g_cnt[p] = 0; g_done[p] = 0; }
            }
            if (pref != p) {
                int old = atomicAdd(&g_done[pref], 1);
                if (old == T_ * K2_PER_IMG - 1) { g_cnt[pref] = 0; g_done[pref] = 0; }
            }
            {
                int old = atomicAdd(&g_tdone, 1);
                if (old == K2GRID - 1) { g_tcnt = 0; g_tdone = 0; }
            }
        }
        __syncthreads();
        const int pref = s_pref;
        const int pb = p * C_;
        const int rb = pref * C_;

        if (tid < 6) {
            const int pl = (tid < 3) ? (pb + tid) : (rb + tid - 3);
            float m = FLT_MAX, M = -FLT_MAX;
            #pragma unroll
            for (int s = 0; s < SLABS; s++) {
                m = fminf(m, g_smin[pl * SLABS + s]);
                M = fmaxf(M, g_smax[pl * SLABS + s]);
            }
            s_m[tid] = m;
            s_M[tid] = M;
        }
        __syncthreads();

        const float a0 = 0.299f / (s_M[0] - s_m[0] + 1e-8f);
        const float a1 = 0.587f / (s_M[1] - s_m[1] + 1e-8f);
        const float a2 = 0.114f / (s_M[2] - s_m[2] + 1e-8f);
        const float bias = -(a0 * s_m[0] + a1 * s_m[1] + a2 * s_m[2]);
        const float b0 = 0.299f / (s_M[3] - s_m[3] + 1e-8f);
        const float b1 = 0.587f / (s_M[4] - s_m[4] + 1e-8f);
        const float b2 = 0.114f / (s_M[5] - s_m[5] + 1e-8f);
        const float rbias = -(b0 * s_m[3] + b1 * s_m[4] + b2 * s_m[5]);

        const size_t roff = (size_t)r0 * 256;
        const float4* __restrict__ c0 = reinterpret_cast<const float4*>(x + (size_t)pb * HW + roff);
        const float4* __restrict__ c1 = reinterpret_cast<const float4*>(x + (size_t)(pb+1) * HW + roff);
        const float4* __restrict__ c2 = reinterpret_cast<const float4*>(x + (size_t)(pb+2) * HW + roff);
        const float4* __restrict__ d0 = reinterpret_cast<const float4*>(x + (size_t)rb * HW + roff);
        const float4* __restrict__ d1 = reinterpret_cast<const float4*>(x + (size_t)(rb+1) * HW + roff);
        const float4* __restrict__ d2 = reinterpret_cast<const float4*>(x + (size_t)(rb+2) * HW + roff);
        float4* __restrict__ o0 = reinterpret_cast<float4*>(xp + (size_t)p * PAIR_STRIDE + roff);
        float4* __restrict__ o1 = reinterpret_cast<float4*>(xp + (size_t)p * PAIR_STRIDE + HW + roff);

        #pragma unroll 2
        for (int q = tid; q < SROWS2 * 64; q += 256) {
            const float4 v0 = __ldg(c0 + q);
            const float4 v1 = __ldg(c1 + q);
            const float4 v2 = __ldg(c2 + q);
            const float4 u0 = __ldg(d0 + q);
            const float4 u1 = __ldg(d1 + q);
            const float4 u2 = __ldg(d2 + q);
            float4 o;
            o.x = a0 * v0.x + a1 * v1.x + a2 * v2.x + bias;
            o.y = a0 * v0.y + a1 * v1.y + a2 * v2.y + bias;
            o.z = a0 * v0.z + a1 * v1.z + a2 * v2.z + bias;
            o.w = a0 * v0.w + a1 * v1.w + a2 * v2.w + bias;
            __stcs(o0 + q, o);
            float4 r;
            r.x = b0 * u0.x + b1 * u1.x + b2 * u2.x + rbias;
            r.y = b0 * u0.y + b1 * u1.y + b2 * u2.y + rbias;
            r.z = b0 * u0.z + b1 * u1.z + b2 * u2.z + rbias;
            r.w = b0 * u0.w + b1 * u1.w + b2 * u2.w + rbias;
            __stcs(o1 + q, r);
        }
    }
}

// ---------------------------------------------------------------------------
extern "C" void kernel_launch(void* const* d_in, const int* in_sizes, int n_in,
                              void* d_out, int out_size) {
    const float* x      = (const float*)d_in[0];
    const int*   dates  = (const int*)d_in[1];
    const float* thetas = (const float*)d_in[2];
    float* out = (float*)d_out;
    float* xp  = out + OUT_ELEMS;

    k_fused<<<K1GRID + K2GRID, 256>>>(x, dates, thetas, out, xp);
}

// round 15
// speedup vs baseline: 1.1217x; 1.1217x over previous
#include <cuda_runtime.h>
#include <cfloat>

// Problem dims (fixed): N=4, T=24, C=4, H=W=256
#define N_ 4
#define T_ 24
#define C_ 4
#define HW 65536
#define NPLANES (N_*T_*C_)   // 384
#define NIMG (N_*T_)         // 96
#define OUT_ELEMS (NPLANES*HW)
#define PAIR_STRIDE (2*HW)

#define ROWS 16              // K1 source rows per slab
#define SLABS (256/ROWS)     // 16
#define K1GRID (NPLANES*SLABS)       // 6144
#define SROWS2 32            // K2 rows per slab
#define SSLABS2 (256/SROWS2) // 8
#define K2GRID (NIMG*SSLABS2)        // 768
#define K2_PER_IMG SSLABS2           // 8
#define CNT_TARGET (3*SLABS)         // 48 (c<3 planes only)

__device__ float g_smin[NPLANES * SLABS];
__device__ float g_smax[NPLANES * SLABS];
__device__ int   g_tidx[N_];
// Flow-control state (zero-init at load; protocol restores zeros each launch)
__device__ int   g_cnt[NIMG];
__device__ int   g_done[NIMG];
__device__ int   g_tcnt;
__device__ int   g_tdone;

__device__ __forceinline__ void poll_geq(const int* p, int target) {
    while (true) {
        int v;
        asm volatile("ld.global.acquire.gpu.b32 %0, [%1];" : "=r"(v) : "l"(p));
        if (v >= target) break;
        __nanosleep(200);
    }
}

__device__ __forceinline__ float4 ld_guard(const float4* __restrict__ row, int A) {
    return ((unsigned)A < 64u) ? row[A] : make_float4(0.f, 0.f, 0.f, 0.f);
}

template<int OFF>
__device__ __forceinline__ float4 hblend(const float4* __restrict__ row, int A,
                                         float wxc, float wx) {
    const float4 v = ld_guard(row, A);
    const float4 w = ld_guard(row, A + 1);
    const float e0 = (OFF == 0) ? v.x : (OFF == 1) ? v.y : (OFF == 2) ? v.z : v.w;
    const float e1 = (OFF == 0) ? v.y : (OFF == 1) ? v.z : (OFF == 2) ? v.w : w.x;
    const float e2 = (OFF == 0) ? v.z : (OFF == 1) ? v.w : (OFF == 2) ? w.x : w.y;
    const float e3 = (OFF == 0) ? v.w : (OFF == 1) ? w.x : (OFF == 2) ? w.y : w.z;
    const float e4 = (OFF == 0) ? w.x : (OFF == 1) ? w.y : (OFF == 2) ? w.z : w.w;
    float4 h;
    h.x = wxc * e0 + wx * e1;
    h.y = wxc * e1 + wx * e2;
    h.z = wxc * e2 + wx * e3;
    h.w = wxc * e3 + wx * e4;
    return h;
}

__device__ __forceinline__ float4 vblend(float4 h0, float4 h1, float wyc, float wy) {
    float4 o;
    o.x = wyc * h0.x + wy * h1.x;
    o.y = wyc * h0.y + wy * h1.y;
    o.z = wyc * h0.z + wy * h1.z;
    o.w = wyc * h0.w + wy * h1.w;
    return o;
}

template<int OFF>
__device__ __forceinline__ void translate_body(
    const float4* __restrict__ sraw,    // [17][64]
    float4* __restrict__ dst4,
    int r0, int DXd, int DY,
    float wx, float wxc, float wy, float wyc, int tid)
{
    const int istart = max(0, r0 - DY);
    const int iend   = min(256, r0 + ROWS - DY);
    const int nrows  = iend - istart;

    if (nrows == ROWS) {
        // Paired-row interior fast path: rows (2g,2g+1),(2g+8,2g+9).
        const int c4 = tid & 63;
        const int g  = tid >> 6;
        const int A  = c4 + DXd;
        const int rA = 2 * g;
        const int rB = 2 * g + 8;
        const float4 hA0 = hblend<OFF>(sraw + rA * 64, A, wxc, wx);
        const float4 hA1 = hblend<OFF>(sraw + (rA + 1) * 64, A, wxc, wx);
        const float4 hA2 = hblend<OFF>(sraw + (rA + 2) * 64, A, wxc, wx);
        const float4 hB0 = hblend<OFF>(sraw + rB * 64, A, wxc, wx);
        const float4 hB1 = hblend<OFF>(sraw + (rB + 1) * 64, A, wxc, wx);
        const float4 hB2 = hblend<OFF>(sraw + (rB + 2) * 64, A, wxc, wx);
        __stcs(dst4 + (istart + rA) * 64 + c4,     vblend(hA0, hA1, wyc, wy));
        __stcs(dst4 + (istart + rA + 1) * 64 + c4, vblend(hA1, hA2, wyc, wy));
        __stcs(dst4 + (istart + rB) * 64 + c4,     vblend(hB0, hB1, wyc, wy));
        __stcs(dst4 + (istart + rB + 1) * 64 + c4, vblend(hB1, hB2, wyc, wy));
    } else {
        for (int q = tid; q < nrows * 64; q += 256) {
            const int rr = q >> 6;
            const int c4 = q & 63;
            const int i = istart + rr;
            const int l0 = i + DY - r0;
            const int A = c4 + DXd;
            const float4 h0 = hblend<OFF>(sraw + l0 * 64, A, wxc, wx);
            const float4 h1 = hblend<OFF>(sraw + (l0 + 1) * 64, A, wxc, wx);
            __stcs(dst4 + i * 64 + c4, vblend(h0, h1, wyc, wy));
        }
    }

    if (r0 == 0 && DY <= -1) {
        const int i = -DY - 1;
        if (i < 256 && tid < 64) {
            const float4 h0 = hblend<OFF>(sraw, tid + DXd, wxc, wx);
            float4 o;
            o.x = wy * h0.x; o.y = wy * h0.y; o.z = wy * h0.z; o.w = wy * h0.w;
            __stcs(dst4 + i * 64 + tid, o);
        }
    }
}

// ---------------------------------------------------------------------------
// Fused kernel: blocks [0, 6144) = translate (+min/max for c<3), publishing
// per-image counters; blocks [6144, 6912) = slice, acquire-polling counters.
// ---------------------------------------------------------------------------
__global__ __launch_bounds__(256) void k_fused(
    const float* __restrict__ x,
    const int* __restrict__ dates,
    const float* __restrict__ thetas,
    float* __restrict__ out,
    float* __restrict__ xp)
{
    const int tid = threadIdx.x;

    if (blockIdx.x < K1GRID) {
        // ================= K1 path =================
        __shared__ float4 sraw[(ROWS + 1) * 64];
        __shared__ float smin[8], smax[8];

        const int plane = blockIdx.x >> 4;        // / SLABS
        const int slab  = blockIdx.x & (SLABS - 1);
        const int r0 = slab * ROWS;
        const int b = plane >> 2;
        const bool do_mm = ((plane & 3) != 3);    // channel 3 min/max unused
        const float* __restrict__ src = x + (size_t)plane * HW;
        float4* __restrict__ dst4 = reinterpret_cast<float4*>(out + (size_t)plane * HW);

        if (blockIdx.x < N_ && tid == 0) {
            const int n = blockIdx.x;
            int best = 0;
            int bd = abs(182 - dates[n * T_]);
            #pragma unroll
            for (int t = 1; t < T_; t++) {
                int d = abs(182 - dates[n * T_ + t]);
                if (d < bd) { bd = d; best = t; }
            }
            g_tidx[n] = best;
            __threadfence();
            atomicAdd(&g_tcnt, 1);
        }

        const float tx = thetas[2 * b + 0];
        const float ty = thetas[2 * b + 1];
        const float fDX = floorf(-tx);
        const float fDY = floorf(-ty);
        const int DX = (int)fDX;
        const int DY = (int)fDY;
        const float wx = -tx - fDX;
        const float wy = -ty - fDY;
        const float wxc = 1.f - wx;
        const float wyc = 1.f - wy;
        const int DXd = DX >> 2;
        const int off = DX & 3;

        // ---- Stage rows r0..r0+15 (unguarded, front-batched) + guarded tail.
        //      Min/max fused only for channels 0..2.
        float vmin = FLT_MAX, vmax = -FLT_MAX;
        const float4* __restrict__ src4 = reinterpret_cast<const float4*>(src);
        {
            float4 vv[4];
            #pragma unroll
            for (int k = 0; k < 4; k++)
                vv[k] = __ldg(src4 + r0 * 64 + tid + k * 256);
            #pragma unroll
            for (int k = 0; k < 4; k++) {
                sraw[tid + k * 256] = vv[k];
                if (do_mm) {
                    vmin = fminf(vmin, fminf(fminf(vv[k].x, vv[k].y), fminf(vv[k].z, vv[k].w)));
                    vmax = fmaxf(vmax, fmaxf(fmaxf(vv[k].x, vv[k].y), fmaxf(vv[k].z, vv[k].w)));
                }
            }
            if (tid < 64) {
                const int gr = r0 + ROWS;
                float4 v = make_float4(0.f, 0.f, 0.f, 0.f);
                if (gr < 256) v = __ldg(src4 + gr * 64 + tid);
                sraw[ROWS * 64 + tid] = v;
            }
        }
        __syncthreads();

        switch (off) {
            case 0: translate_body<0>(sraw, dst4, r0, DXd, DY, wx, wxc, wy, wyc, tid); break;
            case 1: translate_body<1>(sraw, dst4, r0, DXd, DY, wx, wxc, wy, wyc, tid); break;
            case 2: translate_body<2>(sraw, dst4, r0, DXd, DY, wx, wxc, wy, wyc, tid); break;
            default: translate_body<3>(sraw, dst4, r0, DXd, DY, wx, wxc, wy, wyc, tid); break;
        }

        // ---- Zero-fill rows no block computes ----
        {
            const int lo = max(0, -DY - 1);
            const int hi = min(256, 256 - DY);
            const float4 z = make_float4(0.f, 0.f, 0.f, 0.f);
            #pragma unroll
            for (int k = 0; k < 4; k++) {
                const int q = tid + k * 256;
                const int r = r0 + (q >> 6);
                if (r < lo || r >= hi)
                    __stcs(dst4 + r * 64 + (q & 63), z);
            }
        }

        // ---- Block min/max -> per-slab partial + publish (c<3 only) ----
        if (do_mm) {
            #pragma unroll
            for (int o = 16; o; o >>= 1) {
                vmin = fminf(vmin, __shfl_xor_sync(0xffffffffu, vmin, o));
                vmax = fmaxf(vmax, __shfl_xor_sync(0xffffffffu, vmax, o));
            }
            const int w = tid >> 5, l = tid & 31;
            if (l == 0) { smin[w] = vmin; smax[w] = vmax; }
            __syncthreads();
            if (tid == 0) {
                float m = smin[0], M = smax[0];
                #pragma unroll
                for (int k = 1; k < 8; k++) {
                    m = fminf(m, smin[k]);
                    M = fmaxf(M, smax[k]);
                }
                g_smin[plane * SLABS + slab] = m;
                g_smax[plane * SLABS + slab] = M;
                __threadfence();
                atomicAdd(&g_cnt[plane >> 2], 1);
            }
        }
    } else {
        // ================= K2 path =================
        __shared__ float s_m[6], s_M[6];
        __shared__ int s_pref;

        const int k2   = blockIdx.x - K1GRID;
        const int p    = k2 >> 3;                // / SSLABS2
        const int slab = k2 & (SSLABS2 - 1);
        const int n = p / T_;
        const int r0 = slab * SROWS2;

        if (tid == 0) {
            poll_geq(&g_tcnt, N_);
            const int pref = n * T_ + g_tidx[n];
            s_pref = pref;
            poll_geq(&g_cnt[p], CNT_TARGET);
            if (pref != p) poll_geq(&g_cnt[pref], CNT_TARGET);
            // Done tokens: last poller of a counter resets it for next launch.
            {
                const int tgt_p = (p == pref) ? (T_ * K2_PER_IMG) : K2_PER_IMG;
                int old = atomicAdd(&g_done[p], 1);
                if (old == tgt_p - 1) { g_cnt[p] = 0; g_done[p] = 0; }
            }
            if (pref != p) {
                int old = atomicAdd(&g_done[pref], 1);
                if (old == T_ * K2_PER_IMG - 1) { g_cnt[pref] = 0; g_done[pref] = 0; }
            }
            {
                int old = atomicAdd(&g_tdone, 1);
                if (old == K2GRID - 1) { g_tcnt = 0; g_tdone = 0; }
            }
        }
        __syncthreads();
        const int pref = s_pref;
        const int pb = p * C_;
        const int rb = pref * C_;

        if (tid < 6) {
            const int pl = (tid < 3) ? (pb + tid) : (rb + tid - 3);
            float m = FLT_MAX, M = -FLT_MAX;
            #pragma unroll
            for (int s = 0; s < SLABS; s++) {
                m = fminf(m, g_smin[pl * SLABS + s]);
                M = fmaxf(M, g_smax[pl * SLABS + s]);
            }
            s_m[tid] = m;
            s_M[tid] = M;
        }
        __syncthreads();

        const float a0 = 0.299f / (s_M[0] - s_m[0] + 1e-8f);
        const float a1 = 0.587f / (s_M[1] - s_m[1] + 1e-8f);
        const float a2 = 0.114f / (s_M[2] - s_m[2] + 1e-8f);
        const float bias = -(a0 * s_m[0] + a1 * s_m[1] + a2 * s_m[2]);
        const float b0 = 0.299f / (s_M[3] - s_m[3] + 1e-8f);
        const float b1 = 0.587f / (s_M[4] - s_m[4] + 1e-8f);
        const float b2 = 0.114f / (s_M[5] - s_m[5] + 1e-8f);
        const float rbias = -(b0 * s_m[3] + b1 * s_m[4] + b2 * s_m[5]);

        const size_t roff = (size_t)r0 * 256;
        const float4* __restrict__ c0 = reinterpret_cast<const float4*>(x + (size_t)pb * HW + roff);
        const float4* __restrict__ c1 = reinterpret_cast<const float4*>(x + (size_t)(pb+1) * HW + roff);
        const float4* __restrict__ c2 = reinterpret_cast<const float4*>(x + (size_t)(pb+2) * HW + roff);
        const float4* __restrict__ d0 = reinterpret_cast<const float4*>(x + (size_t)rb * HW + roff);
        const float4* __restrict__ d1 = reinterpret_cast<const float4*>(x + (size_t)(rb+1) * HW + roff);
        const float4* __restrict__ d2 = reinterpret_cast<const float4*>(x + (size_t)(rb+2) * HW + roff);
        float4* __restrict__ o0 = reinterpret_cast<float4*>(xp + (size_t)p * PAIR_STRIDE + roff);
        float4* __restrict__ o1 = reinterpret_cast<float4*>(xp + (size_t)p * PAIR_STRIDE + HW + roff);

        #pragma unroll 2
        for (int q = tid; q < SROWS2 * 64; q += 256) {
            const float4 v0 = __ldcs(c0 + q);
            const float4 v1 = __ldcs(c1 + q);
            const float4 v2 = __ldcs(c2 + q);
            const float4 u0 = __ldg(d0 + q);
            const float4 u1 = __ldg(d1 + q);
            const float4 u2 = __ldg(d2 + q);
            float4 o;
            o.x = a0 * v0.x + a1 * v1.x + a2 * v2.x + bias;
            o.y = a0 * v0.y + a1 * v1.y + a2 * v2.y + bias;
            o.z = a0 * v0.z + a1 * v1.z + a2 * v2.z + bias;
            o.w = a0 * v0.w + a1 * v1.w + a2 * v2.w + bias;
            __stcs(o0 + q, o);
            float4 r;
            r.x = b0 * u0.x + b1 * u1.x + b2 * u2.x + rbias;
            r.y = b0 * u0.y + b1 * u1.y + b2 * u2.y + rbias;
            r.z = b0 * u0.z + b1 * u1.z + b2 * u2.z + rbias;
            r.w = b0 * u0.w + b1 * u1.w + b2 * u2.w + rbias;
            __stcs(o1 + q, r);
        }
    }
}

// ---------------------------------------------------------------------------
extern "C" void kernel_launch(void* const* d_in, const int* in_sizes, int n_in,
                              void* d_out, int out_size) {
    const float* x      = (const float*)d_in[0];
    const int*   dates  = (const int*)d_in[1];
    const float* thetas = (const float*)d_in[2];
    float* out = (float*)d_out;
    float* xp  = out + OUT_ELEMS;

    k_fused<<<K1GRID + K2GRID, 256>>>(x, dates, thetas, out, xp);
}